// round 2
// baseline (speedup 1.0000x reference)
#include <cuda_runtime.h>
#include <cstddef>

// Problem dims (fixed)
#define NSAMP 2048
#define JDIM  192
#define KDIM  192
#define R1D   256
#define R2D   48
#define R3D   48

// Scratch (reused across stages):
//   g_buf1: T1 [(n,k), r2] then U1 [(n,k), r2]   (2048*192*48)
//   g_buf2: Y  [n, r3*48+r2] then S [n, m]       (2048*2304)
__device__ float g_buf1[(size_t)NSAMP * KDIM * R2D];
__device__ float g_buf2[(size_t)NSAMP * R2D * R3D];
__device__ float g_Amat[(size_t)NSAMP * R1D];
__device__ float g_smA [(size_t)NSAMP * R1D];
__device__ float g_smB [JDIM * R2D];
__device__ float g_smC [KDIM * R3D];

// ---------------------------------------------------------------------------
// Row softmax for 192x48 matrices (B, C). One thread per row.
// ---------------------------------------------------------------------------
__global__ void k_softmax48(const float* __restrict__ in, float* __restrict__ out) {
    int r = blockIdx.x * blockDim.x + threadIdx.x;
    if (r >= 192) return;
    const float* p = in + r * 48;
    float m = -1e30f;
    #pragma unroll
    for (int j = 0; j < 48; j++) m = fmaxf(m, p[j]);
    float e[48];
    float s = 0.f;
    #pragma unroll
    for (int j = 0; j < 48; j++) { e[j] = expf(p[j] - m); s += e[j]; }
    float inv = 1.f / s;
    #pragma unroll
    for (int j = 0; j < 48; j++) out[r * 48 + j] = e[j] * inv;
}

// ---------------------------------------------------------------------------
// encode1: T1[(n,k), r2] = sum_j X[n][k*192+j] * B_inv[r2][j]
// Rows of X (length 192) are contiguous per (n,k). One thread per row,
// 48 accumulators, B_inv transposed in SMEM (broadcast reads).
// ---------------------------------------------------------------------------
__global__ void __launch_bounds__(256) k_encode1(
    const float* __restrict__ X, const float* __restrict__ B_inv,
    float* __restrict__ T1)
{
    __shared__ float Bs[192][48];   // Bs[j][r2] = B_inv[r2*192+j]
    int tid = threadIdx.x;
    for (int i = tid; i < 192 * 48; i += 256)
        Bs[i % 192][i / 192] = B_inv[i];
    __syncthreads();

    size_t row = (size_t)blockIdx.x * 256 + tid;
    const float4* x4 = (const float4*)(X + row * 192);

    float acc[48];
    #pragma unroll
    for (int c = 0; c < 48; c++) acc[c] = 0.f;

    #pragma unroll 2
    for (int q = 0; q < 48; q++) {
        float4 xv = x4[q];
        int j = q * 4;
        #pragma unroll
        for (int d = 0; d < 4; d++) {
            float xx = (d == 0) ? xv.x : (d == 1) ? xv.y : (d == 2) ? xv.z : xv.w;
            const float4* brow = (const float4*)Bs[j + d];
            #pragma unroll
            for (int c4 = 0; c4 < 12; c4++) {
                float4 b = brow[c4];
                acc[c4*4+0] = fmaf(xx, b.x, acc[c4*4+0]);
                acc[c4*4+1] = fmaf(xx, b.y, acc[c4*4+1]);
                acc[c4*4+2] = fmaf(xx, b.z, acc[c4*4+2]);
                acc[c4*4+3] = fmaf(xx, b.w, acc[c4*4+3]);
            }
        }
    }
    float4* o = (float4*)(T1 + row * 48);
    #pragma unroll
    for (int c4 = 0; c4 < 12; c4++)
        o[c4] = make_float4(acc[c4*4], acc[c4*4+1], acc[c4*4+2], acc[c4*4+3]);
}

// ---------------------------------------------------------------------------
// encode2: Y[n][r3*48+r2] = sum_k C_inv[r3][k] * T1[(n,k)][r2]
// One CTA per sample. T-tile (192x48) and C_inv (48x192) in dynamic SMEM (72KB).
// 192 threads: r2 = tid%48, grp = tid/48; each thread owns 12 r3 rows.
// ---------------------------------------------------------------------------
__global__ void __launch_bounds__(192) k_encode2(
    const float* __restrict__ T1, const float* __restrict__ C_inv,
    float* __restrict__ Y)
{
    extern __shared__ float sm[];
    float* Ts = sm;          // 9216 floats, flat [k*48+r2]
    float* Cs = sm + 9216;   // 9216 floats, flat [r3*192+k]
    int n = blockIdx.x, tid = threadIdx.x;
    const float* Tn = T1 + (size_t)n * 9216;
    for (int i = tid; i < 9216; i += 192) { Ts[i] = Tn[i]; Cs[i] = C_inv[i]; }
    __syncthreads();

    int r2 = tid % 48, grp = tid / 48;
    float acc[12];
    #pragma unroll
    for (int i = 0; i < 12; i++) acc[i] = 0.f;

    for (int k4 = 0; k4 < 192; k4 += 4) {
        float t0 = Ts[(k4+0)*48 + r2];
        float t1 = Ts[(k4+1)*48 + r2];
        float t2 = Ts[(k4+2)*48 + r2];
        float t3 = Ts[(k4+3)*48 + r2];
        #pragma unroll
        for (int i = 0; i < 12; i++) {
            const float4 cv = *(const float4*)&Cs[(grp*12 + i)*192 + k4];
            acc[i] = fmaf(cv.x, t0, fmaf(cv.y, t1, fmaf(cv.z, t2, fmaf(cv.w, t3, acc[i]))));
        }
    }
    float* Yn = Y + (size_t)n * 2304;
    #pragma unroll
    for (int i = 0; i < 12; i++) Yn[(grp*12 + i)*48 + r2] = acc[i];
}

// ---------------------------------------------------------------------------
// Classic tiled SGEMM: C[M,N] = A[M,K] @ B[K,N] (row-major), 64x64x16 tiles,
// 256 threads, 4x4 per thread. RELU_B applies relu to B on load (fuses relu(G)).
// Requires M,N % 64 == 0 and K % 16 == 0.
// ---------------------------------------------------------------------------
template <bool RELU_B>
__global__ void __launch_bounds__(256) k_gemm64(
    const float* __restrict__ A, const float* __restrict__ B,
    float* __restrict__ C, int M, int N, int K)
{
    __shared__ float As[16][68];   // padded, rows stay 16B-aligned (68*4=272=17*16)
    __shared__ float Bs[16][64];
    int tid = threadIdx.x;
    int tx = tid % 16, ty = tid / 16;
    int m0 = blockIdx.y * 64, n0 = blockIdx.x * 64;

    int la_m = tid >> 2;          // 0..63
    int la_k = (tid & 3) << 2;    // 0,4,8,12
    int lb_k = tid >> 4;          // 0..15
    int lb_n = (tid & 15) << 2;   // 0..60

    const float* Aptr = A + (size_t)(m0 + la_m) * K + la_k;
    const float* Bptr = B + (size_t)lb_k * N + (n0 + lb_n);

    float acc[4][4];
    #pragma unroll
    for (int i = 0; i < 4; i++)
        #pragma unroll
        for (int j = 0; j < 4; j++) acc[i][j] = 0.f;

    for (int k0 = 0; k0 < K; k0 += 16) {
        float4 av = *(const float4*)Aptr;
        float4 bv = *(const float4*)Bptr;
        if (RELU_B) {
            bv.x = fmaxf(bv.x, 0.f); bv.y = fmaxf(bv.y, 0.f);
            bv.z = fmaxf(bv.z, 0.f); bv.w = fmaxf(bv.w, 0.f);
        }
        As[la_k+0][la_m] = av.x; As[la_k+1][la_m] = av.y;
        As[la_k+2][la_m] = av.z; As[la_k+3][la_m] = av.w;
        *(float4*)&Bs[lb_k][lb_n] = bv;
        __syncthreads();

        #pragma unroll
        for (int kk = 0; kk < 16; kk++) {
            float4 a = *(const float4*)&As[kk][ty * 4];
            float4 b = *(const float4*)&Bs[kk][tx * 4];
            acc[0][0]=fmaf(a.x,b.x,acc[0][0]); acc[0][1]=fmaf(a.x,b.y,acc[0][1]);
            acc[0][2]=fmaf(a.x,b.z,acc[0][2]); acc[0][3]=fmaf(a.x,b.w,acc[0][3]);
            acc[1][0]=fmaf(a.y,b.x,acc[1][0]); acc[1][1]=fmaf(a.y,b.y,acc[1][1]);
            acc[1][2]=fmaf(a.y,b.z,acc[1][2]); acc[1][3]=fmaf(a.y,b.w,acc[1][3]);
            acc[2][0]=fmaf(a.z,b.x,acc[2][0]); acc[2][1]=fmaf(a.z,b.y,acc[2][1]);
            acc[2][2]=fmaf(a.z,b.z,acc[2][2]); acc[2][3]=fmaf(a.z,b.w,acc[2][3]);
            acc[3][0]=fmaf(a.w,b.x,acc[3][0]); acc[3][1]=fmaf(a.w,b.y,acc[3][1]);
            acc[3][2]=fmaf(a.w,b.z,acc[3][2]); acc[3][3]=fmaf(a.w,b.w,acc[3][3]);
        }
        __syncthreads();
        Aptr += 16;
        Bptr += (size_t)16 * N;
    }
    #pragma unroll
    for (int i = 0; i < 4; i++) {
        float4 v = make_float4(acc[i][0], acc[i][1], acc[i][2], acc[i][3]);
        *(float4*)(C + (size_t)(m0 + ty*4 + i) * N + n0 + tx*4) = v;
    }
}

// ---------------------------------------------------------------------------
// Row softmax for A (2048 x 256). One CTA of 256 threads per row.
// ---------------------------------------------------------------------------
__global__ void __launch_bounds__(256) k_softmaxA(
    const float* __restrict__ A, float* __restrict__ out)
{
    __shared__ float red[8];
    int n = blockIdx.x, t = threadIdx.x;
    float v = A[(size_t)n * 256 + t];
    float m = v;
    #pragma unroll
    for (int o = 16; o > 0; o >>= 1) m = fmaxf(m, __shfl_xor_sync(0xffffffffu, m, o));
    if ((t & 31) == 0) red[t >> 5] = m;
    __syncthreads();
    float bm = red[0];
    #pragma unroll
    for (int i = 1; i < 8; i++) bm = fmaxf(bm, red[i]);
    float e = expf(v - bm);
    float s = e;
    #pragma unroll
    for (int o = 16; o > 0; o >>= 1) s += __shfl_xor_sync(0xffffffffu, s, o);
    __syncthreads();
    if ((t & 31) == 0) red[t >> 5] = s;
    __syncthreads();
    float bs = 0.f;
    #pragma unroll
    for (int i = 0; i < 8; i++) bs += red[i];
    out[(size_t)n * 256 + t] = e / bs;
}

// ---------------------------------------------------------------------------
// decode1: U1[(n,k)][r2] = sum_r3 smC[k][r3] * S[n][r3*48+r2]
// One CTA per sample; S row (2304) + smC (padded to 49) in SMEM. Thread = k.
// ---------------------------------------------------------------------------
__global__ void __launch_bounds__(192) k_decode1(
    const float* __restrict__ S, const float* __restrict__ smC,
    float* __restrict__ U1)
{
    __shared__ float Ss[2304];
    __shared__ float Cs[192][49];   // padded: conflict-free per-lane rows
    int n = blockIdx.x, tid = threadIdx.x;
    const float* Sn = S + (size_t)n * 2304;
    for (int i = tid; i < 2304; i += 192) Ss[i] = Sn[i];
    for (int i = tid; i < 9216; i += 192) Cs[i / 48][i % 48] = smC[i];
    __syncthreads();

    float acc[48];
    #pragma unroll
    for (int i = 0; i < 48; i++) acc[i] = 0.f;

    for (int r3 = 0; r3 < 48; r3++) {
        float c = Cs[tid][r3];
        const float4* sr = (const float4*)&Ss[r3 * 48];
        #pragma unroll
        for (int q = 0; q < 12; q++) {
            float4 sv = sr[q];
            acc[q*4+0] = fmaf(c, sv.x, acc[q*4+0]);
            acc[q*4+1] = fmaf(c, sv.y, acc[q*4+1]);
            acc[q*4+2] = fmaf(c, sv.z, acc[q*4+2]);
            acc[q*4+3] = fmaf(c, sv.w, acc[q*4+3]);
        }
    }
    float4* o = (float4*)(U1 + ((size_t)n * 192 + tid) * 48);
    #pragma unroll
    for (int q = 0; q < 12; q++)
        o[q] = make_float4(acc[q*4], acc[q*4+1], acc[q*4+2], acc[q*4+3]);
}

// ---------------------------------------------------------------------------
// decode2: out[(n,k)][j] = sum_r2 U1[(n,k)][r2] * smB[j][r2]
// 64 rows per CTA, 4 threads per row (tx), cols j = tx*4 + 16*i + d
// so each quad's float4 stores are 64B-contiguous.
// ---------------------------------------------------------------------------
__global__ void __launch_bounds__(256) k_decode2(
    const float* __restrict__ U1, const float* __restrict__ smB,
    float* __restrict__ out)
{
    __shared__ float Bs[48][192];   // Bs[r2][j] = smB[j*48+r2]
    int tid = threadIdx.x;
    for (int i = tid; i < 9216; i += 256) Bs[i % 48][i / 48] = smB[i];
    __syncthreads();

    size_t row = (size_t)blockIdx.x * 64 + (tid >> 2);
    int tx = tid & 3;
    const float4* u4 = (const float4*)(U1 + row * 48);

    float acc[12][4];
    #pragma unroll
    for (int i = 0; i < 12; i++)
        #pragma unroll
        for (int d = 0; d < 4; d++) acc[i][d] = 0.f;

    #pragma unroll 3
    for (int q = 0; q < 12; q++) {
        float4 uv = u4[q];
        #pragma unroll
        for (int d = 0; d < 4; d++) {
            int r2 = q * 4 + d;
            float uu = (d == 0) ? uv.x : (d == 1) ? uv.y : (d == 2) ? uv.z : uv.w;
            #pragma unroll
            for (int i = 0; i < 12; i++) {
                float4 b = *(const float4*)&Bs[r2][tx * 4 + 16 * i];
                acc[i][0] = fmaf(uu, b.x, acc[i][0]);
                acc[i][1] = fmaf(uu, b.y, acc[i][1]);
                acc[i][2] = fmaf(uu, b.z, acc[i][2]);
                acc[i][3] = fmaf(uu, b.w, acc[i][3]);
            }
        }
    }
    float* orow = out + row * 192;
    #pragma unroll
    for (int i = 0; i < 12; i++)
        *(float4*)(orow + tx * 4 + 16 * i) =
            make_float4(acc[i][0], acc[i][1], acc[i][2], acc[i][3]);
}

// ---------------------------------------------------------------------------
// Launch pipeline (all default stream -> sequential deps; graph-capturable:
// only kernel launches + non-stream host queries).
// ---------------------------------------------------------------------------
extern "C" void kernel_launch(void* const* d_in, const int* in_sizes, int n_in,
                              void* d_out, int out_size)
{
    const float* X     = (const float*)d_in[0];
    const float* B     = (const float*)d_in[1];
    const float* C     = (const float*)d_in[2];
    const float* G     = (const float*)d_in[3];
    const float* B_inv = (const float*)d_in[4];
    const float* C_inv = (const float*)d_in[5];
    const float* G_inv = (const float*)d_in[6];
    float* out = (float*)d_out;

    float *pBuf1, *pBuf2, *pA, *pSmA, *pSmB, *pSmC;
    cudaGetSymbolAddress((void**)&pBuf1, g_buf1);
    cudaGetSymbolAddress((void**)&pBuf2, g_buf2);
    cudaGetSymbolAddress((void**)&pA,    g_Amat);
    cudaGetSymbolAddress((void**)&pSmA,  g_smA);
    cudaGetSymbolAddress((void**)&pSmB,  g_smB);
    cudaGetSymbolAddress((void**)&pSmC,  g_smC);

    cudaFuncSetAttribute(k_encode2, cudaFuncAttributeMaxDynamicSharedMemorySize, 73728);

    // Factor softmaxes
    k_softmax48<<<1, 192>>>(B, pSmB);
    k_softmax48<<<1, 192>>>(C, pSmC);

    // Encode
    k_encode1<<<1536, 256>>>(X, B_inv, pBuf1);                 // T1
    k_encode2<<<2048, 192, 73728>>>(pBuf1, C_inv, pBuf2);      // Y
    k_gemm64<false><<<dim3(256 / 64, 2048 / 64), 256>>>(pBuf2, G_inv, pA, 2048, 256, 2304); // A
    k_softmaxA<<<2048, 256>>>(pA, pSmA);                       // sm(A)

    // Decode
    k_gemm64<true><<<dim3(2304 / 64, 2048 / 64), 256>>>(pSmA, G, pBuf2, 2048, 2304, 256);   // S (relu fused)
    k_decode1<<<2048, 192>>>(pBuf2, pSmC, pBuf1);              // U1
    k_decode2<<<6144, 256>>>(pBuf1, pSmB, out);                // out
}

// round 3
// speedup vs baseline: 2.3988x; 2.3988x over previous
#include <cuda_runtime.h>
#include <cstdint>
#include <cstddef>

// Problem dims (fixed)
#define NSAMP 2048
#define JDIM  192
#define KDIM  192
#define R1D   256
#define R2D   48
#define R3D   48

// ---------------------------------------------------------------------------
// Scratch (__device__ globals; no allocation)
// ---------------------------------------------------------------------------
__device__ __align__(16) float    g_buf1[(size_t)NSAMP * KDIM * R2D];   // T1 then U1 (75MB)
__device__ __align__(16) float    g_buf2[(size_t)NSAMP * R2D * R3D];    // Y then S  (18MB)
__device__ __align__(16) float    g_Amat[(size_t)NSAMP * R1D];
__device__ __align__(16) float    g_smA [(size_t)NSAMP * R1D];
__device__ __align__(16) uint32_t g_BinvT[R2D * JDIM];     // tf32 B_inv (48x192)
__device__ __align__(16) uint32_t g_CinvT[R3D * KDIM];     // tf32 C_inv (48x192)
__device__ __align__(16) uint32_t g_smBT [JDIM * R2D];     // tf32 softmax(B) (192x48)
__device__ __align__(16) uint32_t g_smCT [KDIM * R3D];     // tf32 softmax(C) (192x48)
__device__ __align__(16) uint32_t g_Gt   [R1D * 2304];     // tf32 G_inv^T (256x2304)
__device__ __align__(16) uint32_t g_Grt  [2304 * R1D];     // tf32 relu(G)^T (2304x256)

// ---------------------------------------------------------------------------
// tf32 helpers
// ---------------------------------------------------------------------------
__device__ __forceinline__ uint32_t cvt_tf32(float x) {
    uint32_t r;
    asm("cvt.rna.tf32.f32 %0, %1;" : "=r"(r) : "f"(x));
    return r;
}

__device__ __forceinline__ void mma_tf32(float* d, const uint32_t* a, const uint32_t* b) {
    asm volatile(
        "mma.sync.aligned.m16n8k8.row.col.f32.tf32.tf32.f32 "
        "{%0,%1,%2,%3},{%4,%5,%6,%7},{%8,%9},{%0,%1,%2,%3};"
        : "+f"(d[0]), "+f"(d[1]), "+f"(d[2]), "+f"(d[3])
        : "r"(a[0]), "r"(a[1]), "r"(a[2]), "r"(a[3]), "r"(b[0]), "r"(b[1]));
}

// ---------------------------------------------------------------------------
// Prep kernels: convert / softmax / transpose into tf32 operand layouts
// ---------------------------------------------------------------------------
__global__ void k_cvt(const float* __restrict__ in, uint32_t* __restrict__ out, int n) {
    int i = blockIdx.x * blockDim.x + threadIdx.x;
    if (i < n) out[i] = cvt_tf32(in[i]);
}

// Row softmax of a 192x48 matrix, output tf32 bits in same layout.
__global__ void k_softmax48_tf(const float* __restrict__ in, uint32_t* __restrict__ out) {
    int r = threadIdx.x;
    if (r >= 192) return;
    const float* p = in + r * 48;
    float m = -1e30f;
    #pragma unroll
    for (int j = 0; j < 48; j++) m = fmaxf(m, p[j]);
    float e[48], s = 0.f;
    #pragma unroll
    for (int j = 0; j < 48; j++) { e[j] = expf(p[j] - m); s += e[j]; }
    float inv = 1.f / s;
    #pragma unroll
    for (int j = 0; j < 48; j++) out[r * 48 + j] = cvt_tf32(e[j] * inv);
}

// Gt[c][r] = tf32(G_inv[r][c]);  G_inv: (2304,256)
__global__ void k_transpose_ginv(const float* __restrict__ Gi, uint32_t* __restrict__ Gt) {
    int idx = blockIdx.x * blockDim.x + threadIdx.x;   // over 2304*256
    int r = idx >> 8, c = idx & 255;
    Gt[c * 2304 + r] = cvt_tf32(Gi[idx]);
}

// Grt[m][c] = tf32(relu(G[c][m]));  G: (256,2304)
__global__ void k_transpose_relug(const float* __restrict__ G, uint32_t* __restrict__ Grt) {
    int idx = blockIdx.x * blockDim.x + threadIdx.x;   // over 256*2304
    int c = idx / 2304, m = idx % 2304;
    Grt[m * 256 + c] = cvt_tf32(fmaxf(G[idx], 0.f));
}

// ---------------------------------------------------------------------------
// Generic tf32 tensor-core GEMM:  C[M,N] = A[M,K] (fp32) @ B[N,K]^T (tf32)
// CTA tile BM x BN, K-chunks of BK. 256 threads = 8 warps as MW x NW grid.
// Requires M%BM==0, N%BN==0, K%BK==0, BK%8==0.
// ---------------------------------------------------------------------------
template <int BM, int BN, int BK, int MW, int NW>
__global__ void __launch_bounds__(256) k_gemm_tc(
    const float* __restrict__ A, const uint32_t* __restrict__ B,
    float* __restrict__ C, int M, int N, int K)
{
    constexpr int WM = BM / MW, WN = BN / NW;
    constexpr int MT = WM / 16, NT = WN / 8;
    constexpr int LDSS = BK + 4;
    __shared__ uint32_t As[BM * LDSS];
    __shared__ uint32_t Bs[BN * LDSS];

    const int tid  = threadIdx.x;
    const int lane = tid & 31, warp = tid >> 5;
    const int wm = (warp / NW) * WM;
    const int wn = (warp % NW) * WN;
    const int m0 = blockIdx.y * BM;
    const int n0 = blockIdx.x * BN;
    const int lr = lane >> 2, lc = lane & 3;

    float acc[MT][NT][4];
    #pragma unroll
    for (int i = 0; i < MT; i++)
        #pragma unroll
        for (int j = 0; j < NT; j++)
            #pragma unroll
            for (int d = 0; d < 4; d++) acc[i][j][d] = 0.f;

    for (int k0 = 0; k0 < K; k0 += BK) {
        // Stage A tile (convert fp32 -> tf32)
        for (int i = tid; i < BM * BK / 4; i += 256) {
            int r = i / (BK / 4), c = (i % (BK / 4)) * 4;
            const float4 v = *(const float4*)(A + (size_t)(m0 + r) * K + k0 + c);
            uint32_t* p = &As[r * LDSS + c];
            p[0] = cvt_tf32(v.x); p[1] = cvt_tf32(v.y);
            p[2] = cvt_tf32(v.z); p[3] = cvt_tf32(v.w);
        }
        // Stage B tile (already tf32)
        for (int i = tid; i < BN * BK / 4; i += 256) {
            int r = i / (BK / 4), c = (i % (BK / 4)) * 4;
            const uint4 v = *(const uint4*)(B + (size_t)(n0 + r) * K + k0 + c);
            uint32_t* p = &Bs[r * LDSS + c];
            p[0] = v.x; p[1] = v.y; p[2] = v.z; p[3] = v.w;
        }
        __syncthreads();

        #pragma unroll
        for (int kk = 0; kk < BK; kk += 8) {
            uint32_t af[MT][4], bf[NT][2];
            #pragma unroll
            for (int mt = 0; mt < MT; mt++) {
                const uint32_t* p = &As[(wm + mt * 16 + lr) * LDSS + kk + lc];
                af[mt][0] = p[0];
                af[mt][1] = p[8 * LDSS];
                af[mt][2] = p[4];
                af[mt][3] = p[8 * LDSS + 4];
            }
            #pragma unroll
            for (int nt = 0; nt < NT; nt++) {
                const uint32_t* p = &Bs[(wn + nt * 8 + lr) * LDSS + kk + lc];
                bf[nt][0] = p[0];
                bf[nt][1] = p[4];
            }
            #pragma unroll
            for (int mt = 0; mt < MT; mt++)
                #pragma unroll
                for (int nt = 0; nt < NT; nt++)
                    mma_tf32(acc[mt][nt], af[mt], bf[nt]);
        }
        __syncthreads();
    }

    #pragma unroll
    for (int mt = 0; mt < MT; mt++) {
        int r0 = m0 + wm + mt * 16 + lr;
        #pragma unroll
        for (int nt = 0; nt < NT; nt++) {
            int c0 = n0 + wn + nt * 8 + 2 * lc;
            *(float2*)(C + (size_t)r0 * N + c0)       = make_float2(acc[mt][nt][0], acc[mt][nt][1]);
            *(float2*)(C + (size_t)(r0 + 8) * N + c0) = make_float2(acc[mt][nt][2], acc[mt][nt][3]);
        }
    }
}

// ---------------------------------------------------------------------------
// encode2 (batched TC): Y[n](48x48) = C_inv(48x192) @ T1[n](192x48)
// A = C_inv (tf32, row-major 48x192), B = T1[n]^T staged+transposed in SMEM.
// 192 threads = 6 warps: warp = (m-tile mt=w%3, n-half nh=w/3 covering 3 n8).
// ---------------------------------------------------------------------------
__global__ void __launch_bounds__(192) k_enc2_tc(
    const float* __restrict__ T1, const uint32_t* __restrict__ Cinv,
    float* __restrict__ Y)
{
    extern __shared__ uint32_t sm2[];
    uint32_t* As = sm2;               // [48][196]
    uint32_t* Bs = sm2 + 48 * 196;    // [48][196]
    const int n = blockIdx.x, tid = threadIdx.x;

    for (int i = tid; i < 2304; i += 192) {          // C_inv: 9216 u32
        int r = i / 48, c = (i % 48) * 4;
        uint4 v = *(const uint4*)(Cinv + r * 192 + c);
        uint32_t* p = &As[r * 196 + c];
        p[0] = v.x; p[1] = v.y; p[2] = v.z; p[3] = v.w;
    }
    const float* Tn = T1 + (size_t)n * 9216;
    for (int i = tid; i < 2304; i += 192) {          // T1[n]: 9216 floats, transpose
        int k = i / 12, r2 = (i % 12) * 4;
        float4 v = *(const float4*)(Tn + k * 48 + r2);
        Bs[(r2 + 0) * 196 + k] = cvt_tf32(v.x);
        Bs[(r2 + 1) * 196 + k] = cvt_tf32(v.y);
        Bs[(r2 + 2) * 196 + k] = cvt_tf32(v.z);
        Bs[(r2 + 3) * 196 + k] = cvt_tf32(v.w);
    }
    __syncthreads();

    const int lane = tid & 31, warp = tid >> 5;
    const int mt = warp % 3, nh = warp / 3;
    const int lr = lane >> 2, lc = lane & 3;

    float acc[3][4];
    #pragma unroll
    for (int i = 0; i < 3; i++)
        #pragma unroll
        for (int d = 0; d < 4; d++) acc[i][d] = 0.f;

    #pragma unroll
    for (int kk = 0; kk < 192; kk += 8) {
        uint32_t af[4];
        const uint32_t* pa = &As[(mt * 16 + lr) * 196 + kk + lc];
        af[0] = pa[0]; af[1] = pa[8 * 196]; af[2] = pa[4]; af[3] = pa[8 * 196 + 4];
        #pragma unroll
        for (int nt = 0; nt < 3; nt++) {
            const uint32_t* pb = &Bs[(nh * 24 + nt * 8 + lr) * 196 + kk + lc];
            uint32_t bf[2] = { pb[0], pb[4] };
            mma_tf32(acc[nt], af, bf);
        }
    }

    float* Yn = Y + (size_t)n * 2304;
    #pragma unroll
    for (int nt = 0; nt < 3; nt++) {
        int r3 = mt * 16 + lr;
        int r2 = nh * 24 + nt * 8 + 2 * lc;
        *(float2*)(Yn + r3 * 48 + r2)       = make_float2(acc[nt][0], acc[nt][1]);
        *(float2*)(Yn + (r3 + 8) * 48 + r2) = make_float2(acc[nt][2], acc[nt][3]);
    }
}

// ---------------------------------------------------------------------------
// decode1 (batched TC): U1[n](192x48) = smC(192x48) @ S[n](48x48)
// A = smC (tf32 row-major, M=192 K=48), B = S[n]^T (48x48 transposed in SMEM).
// 192 threads = 6 warps; warp w covers rows w*32..w*32+31, all 48 cols.
// ---------------------------------------------------------------------------
__global__ void __launch_bounds__(192) k_dec1_tc(
    const float* __restrict__ S, const uint32_t* __restrict__ smC,
    float* __restrict__ U1)
{
    extern __shared__ uint32_t sm3[];
    uint32_t* As = sm3;               // [192][52]
    uint32_t* Bs = sm3 + 192 * 52;    // [48][52]
    const int n = blockIdx.x, tid = threadIdx.x;

    for (int i = tid; i < 2304; i += 192) {          // smC: 9216 u32
        int r = i / 12, c = (i % 12) * 4;
        uint4 v = *(const uint4*)(smC + r * 48 + c);
        uint32_t* p = &As[r * 52 + c];
        p[0] = v.x; p[1] = v.y; p[2] = v.z; p[3] = v.w;
    }
    const float* Sn = S + (size_t)n * 2304;
    for (int i = tid; i < 576; i += 192) {           // S[n]: 2304 floats, transpose
        int r3 = i / 12, r2 = (i % 12) * 4;
        float4 v = *(const float4*)(Sn + r3 * 48 + r2);
        Bs[(r2 + 0) * 52 + r3] = cvt_tf32(v.x);
        Bs[(r2 + 1) * 52 + r3] = cvt_tf32(v.y);
        Bs[(r2 + 2) * 52 + r3] = cvt_tf32(v.z);
        Bs[(r2 + 3) * 52 + r3] = cvt_tf32(v.w);
    }
    __syncthreads();

    const int lane = tid & 31, warp = tid >> 5;
    const int lr = lane >> 2, lc = lane & 3;

    float acc[2][6][4];
    #pragma unroll
    for (int i = 0; i < 2; i++)
        #pragma unroll
        for (int j = 0; j < 6; j++)
            #pragma unroll
            for (int d = 0; d < 4; d++) acc[i][j][d] = 0.f;

    #pragma unroll
    for (int kk = 0; kk < 48; kk += 8) {
        uint32_t af[2][4], bf[6][2];
        #pragma unroll
        for (int mt = 0; mt < 2; mt++) {
            const uint32_t* pa = &As[(warp * 32 + mt * 16 + lr) * 52 + kk + lc];
            af[mt][0] = pa[0]; af[mt][1] = pa[8 * 52];
            af[mt][2] = pa[4]; af[mt][3] = pa[8 * 52 + 4];
        }
        #pragma unroll
        for (int nt = 0; nt < 6; nt++) {
            const uint32_t* pb = &Bs[(nt * 8 + lr) * 52 + kk + lc];
            bf[nt][0] = pb[0]; bf[nt][1] = pb[4];
        }
        #pragma unroll
        for (int mt = 0; mt < 2; mt++)
            #pragma unroll
            for (int nt = 0; nt < 6; nt++)
                mma_tf32(acc[mt][nt], af[mt], bf[nt]);
    }

    float* Un = U1 + (size_t)n * 9216;
    #pragma unroll
    for (int mt = 0; mt < 2; mt++) {
        int kr = warp * 32 + mt * 16 + lr;
        #pragma unroll
        for (int nt = 0; nt < 6; nt++) {
            int r2 = nt * 8 + 2 * lc;
            *(float2*)(Un + kr * 48 + r2)       = make_float2(acc[mt][nt][0], acc[mt][nt][1]);
            *(float2*)(Un + (kr + 8) * 48 + r2) = make_float2(acc[mt][nt][2], acc[mt][nt][3]);
        }
    }
}

// ---------------------------------------------------------------------------
// Row softmax for A (2048 x 256), fp32.
// ---------------------------------------------------------------------------
__global__ void __launch_bounds__(256) k_softmaxA(
    const float* __restrict__ A, float* __restrict__ out)
{
    __shared__ float red[8];
    int n = blockIdx.x, t = threadIdx.x;
    float v = A[(size_t)n * 256 + t];
    float m = v;
    #pragma unroll
    for (int o = 16; o > 0; o >>= 1) m = fmaxf(m, __shfl_xor_sync(0xffffffffu, m, o));
    if ((t & 31) == 0) red[t >> 5] = m;
    __syncthreads();
    float bm = red[0];
    #pragma unroll
    for (int i = 1; i < 8; i++) bm = fmaxf(bm, red[i]);
    float e = expf(v - bm);
    float s = e;
    #pragma unroll
    for (int o = 16; o > 0; o >>= 1) s += __shfl_xor_sync(0xffffffffu, s, o);
    __syncthreads();
    if ((t & 31) == 0) red[t >> 5] = s;
    __syncthreads();
    float bs = 0.f;
    #pragma unroll
    for (int i = 0; i < 8; i++) bs += red[i];
    out[(size_t)n * 256 + t] = e / bs;
}

// ---------------------------------------------------------------------------
// Launch pipeline (default stream -> sequential; graph-capturable)
// ---------------------------------------------------------------------------
extern "C" void kernel_launch(void* const* d_in, const int* in_sizes, int n_in,
                              void* d_out, int out_size)
{
    const float* X     = (const float*)d_in[0];
    const float* B     = (const float*)d_in[1];
    const float* C     = (const float*)d_in[2];
    const float* G     = (const float*)d_in[3];
    const float* B_inv = (const float*)d_in[4];
    const float* C_inv = (const float*)d_in[5];
    const float* G_inv = (const float*)d_in[6];
    float* out = (float*)d_out;

    float *pBuf1, *pBuf2, *pA, *pSmA;
    uint32_t *pBinvT, *pCinvT, *pSmBT, *pSmCT, *pGt, *pGrt;
    cudaGetSymbolAddress((void**)&pBuf1,  g_buf1);
    cudaGetSymbolAddress((void**)&pBuf2,  g_buf2);
    cudaGetSymbolAddress((void**)&pA,     g_Amat);
    cudaGetSymbolAddress((void**)&pSmA,   g_smA);
    cudaGetSymbolAddress((void**)&pBinvT, g_BinvT);
    cudaGetSymbolAddress((void**)&pCinvT, g_CinvT);
    cudaGetSymbolAddress((void**)&pSmBT,  g_smBT);
    cudaGetSymbolAddress((void**)&pSmCT,  g_smCT);
    cudaGetSymbolAddress((void**)&pGt,    g_Gt);
    cudaGetSymbolAddress((void**)&pGrt,   g_Grt);

    cudaFuncSetAttribute(k_enc2_tc, cudaFuncAttributeMaxDynamicSharedMemorySize, 2 * 48 * 196 * 4);
    cudaFuncSetAttribute(k_dec1_tc, cudaFuncAttributeMaxDynamicSharedMemorySize, (192 + 48) * 52 * 4);

    // --- prep: tf32 operand layouts ---
    k_cvt<<<36, 256>>>(B_inv, pBinvT, 48 * 192);
    k_cvt<<<36, 256>>>(C_inv, pCinvT, 48 * 192);
    k_softmax48_tf<<<1, 192>>>(B, pSmBT);
    k_softmax48_tf<<<1, 192>>>(C, pSmCT);
    k_transpose_ginv<<<2304, 256>>>(G_inv, pGt);
    k_transpose_relug<<<2304, 256>>>(G, pGrt);

    // --- encode ---
    // T1 = X(393216x192) @ B_inv^T -> (393216x48)
    k_gemm_tc<128, 48, 64, 8, 1><<<dim3(1, 3072), 256>>>(X, pBinvT, pBuf1, 393216, 48, 192);
    // Y[n] = C_inv @ T1[n]
    k_enc2_tc<<<2048, 192, 2 * 48 * 196 * 4>>>(pBuf1, pCinvT, pBuf2);
    // A = Y(2048x2304) @ G_inv(2304x256)
    k_gemm_tc<64, 64, 32, 2, 4><<<dim3(4, 32), 256>>>(pBuf2, pGt, pA, 2048, 256, 2304);
    k_softmaxA<<<2048, 256>>>(pA, pSmA);

    // --- decode ---
    // S = smA(2048x256) @ relu(G)(256x2304)
    k_gemm_tc<128, 128, 32, 4, 2><<<dim3(18, 16), 256>>>(pSmA, pGrt, pBuf2, 2048, 2304, 256);
    // U1[n] = smC @ S[n]
    k_dec1_tc<<<2048, 192, (192 + 48) * 52 * 4>>>(pBuf2, pSmCT, pBuf1);
    // out = U1(393216x48) @ smB^T -> (393216x192)
    k_gemm_tc<128, 96, 48, 4, 2><<<dim3(2, 3072), 256>>>(pBuf1, pSmBT, out, 393216, 192, 48);
}

// round 4
// speedup vs baseline: 2.9053x; 1.2112x over previous
#include <cuda_runtime.h>
#include <cstdint>
#include <cstddef>

// Problem dims (fixed)
#define NSAMP 2048
#define JDIM  192
#define KDIM  192
#define R1D   256
#define R2D   48
#define R3D   48

// ---------------------------------------------------------------------------
// Scratch (__device__ globals; no allocation)
// ---------------------------------------------------------------------------
__device__ __align__(16) float    g_buf2[(size_t)NSAMP * R2D * R3D];    // Y then S (18MB)
__device__ __align__(16) float    g_Amat[(size_t)NSAMP * R1D];
__device__ __align__(16) float    g_smA [(size_t)NSAMP * R1D];
__device__ __align__(16) uint32_t g_smBT [JDIM * R2D];     // tf32 softmax(B) (192x48)
__device__ __align__(16) uint32_t g_smCT [KDIM * R3D];     // tf32 softmax(C) (192x48)
__device__ __align__(16) uint32_t g_Gt   [R1D * 2304];     // tf32 G_inv^T (256x2304)
__device__ __align__(16) uint32_t g_Grt  [2304 * R1D];     // tf32 relu(G)^T (2304x256)

// ---------------------------------------------------------------------------
// tf32 helpers
// ---------------------------------------------------------------------------
__device__ __forceinline__ uint32_t cvt_tf32(float x) {
    uint32_t r;
    asm("cvt.rna.tf32.f32 %0, %1;" : "=r"(r) : "f"(x));
    return r;
}

__device__ __forceinline__ void mma_tf32(float* d, const uint32_t* a, const uint32_t* b) {
    asm volatile(
        "mma.sync.aligned.m16n8k8.row.col.f32.tf32.tf32.f32 "
        "{%0,%1,%2,%3},{%4,%5,%6,%7},{%8,%9},{%0,%1,%2,%3};"
        : "+f"(d[0]), "+f"(d[1]), "+f"(d[2]), "+f"(d[3])
        : "r"(a[0]), "r"(a[1]), "r"(a[2]), "r"(a[3]), "r"(b[0]), "r"(b[1]));
}

__device__ __forceinline__ void cp_async16(uint32_t smem_dst, const void* gsrc) {
    asm volatile("cp.async.cg.shared.global [%0], [%1], 16;" :: "r"(smem_dst), "l"(gsrc));
}

// ---------------------------------------------------------------------------
// Fused prep: G_inv^T, relu(G)^T (tiled coalesced transposes) + both softmaxes.
// grid = 1154 blocks x 256 threads.
//   [0,576)    : Ginv (2304x256) -> Gt (256x2304), tf32
//   [576,1152) : G (256x2304) -> Grt (2304x256), relu+tf32
//   1152       : softmax rows of B -> g_smBT (tf32)
//   1153       : softmax rows of C -> g_smCT (tf32)
// ---------------------------------------------------------------------------
__global__ void __launch_bounds__(256) k_prep(
    const float* __restrict__ Gi, const float* __restrict__ G,
    const float* __restrict__ B,  const float* __restrict__ C,
    uint32_t* __restrict__ Gt, uint32_t* __restrict__ Grt,
    uint32_t* __restrict__ smBT, uint32_t* __restrict__ smCT)
{
    __shared__ float tile[32][33];
    const int b = blockIdx.x, tid = threadIdx.x;
    const int tx = tid & 31, ty = tid >> 5;

    if (b < 576) {
        // Gt[c][r] = tf32(Ginv[r][c]);  Ginv: 2304x256
        int br = b >> 3, bc = b & 7;
        #pragma unroll
        for (int i = 0; i < 4; i++)
            tile[ty + 8*i][tx] = Gi[(size_t)(br*32 + ty + 8*i) * 256 + bc*32 + tx];
        __syncthreads();
        #pragma unroll
        for (int i = 0; i < 4; i++)
            Gt[(size_t)(bc*32 + ty + 8*i) * 2304 + br*32 + tx] = cvt_tf32(tile[tx][ty + 8*i]);
    } else if (b < 1152) {
        // Grt[m][c] = tf32(relu(G[c][m]));  G: 256x2304
        int b2 = b - 576;
        int br = b2 & 7, bc = b2 >> 3;   // br: G row tiles (8), bc: G col tiles (72)
        #pragma unroll
        for (int i = 0; i < 4; i++)
            tile[ty + 8*i][tx] = G[(size_t)(br*32 + ty + 8*i) * 2304 + bc*32 + tx];
        __syncthreads();
        #pragma unroll
        for (int i = 0; i < 4; i++)
            Grt[(size_t)(bc*32 + ty + 8*i) * 256 + br*32 + tx] =
                cvt_tf32(fmaxf(tile[tx][ty + 8*i], 0.f));
    } else {
        const float* in = (b == 1152) ? B : C;
        uint32_t* out = (b == 1152) ? smBT : smCT;
        int r = tid;
        if (r < 192) {
            const float* p = in + r * 48;
            float m = -1e30f;
            #pragma unroll
            for (int j = 0; j < 48; j++) m = fmaxf(m, p[j]);
            float e[48], s = 0.f;
            #pragma unroll
            for (int j = 0; j < 48; j++) { e[j] = expf(p[j] - m); s += e[j]; }
            float inv = 1.f / s;
            #pragma unroll
            for (int j = 0; j < 48; j++) out[r * 48 + j] = cvt_tf32(e[j] * inv);
        }
    }
}

// ---------------------------------------------------------------------------
// Fused encode: one CTA per sample n (192 threads = 6 warps).
//   stage1: T[k][r2] = sum_j X[n][k*192+j] * B_inv[r2][j]   (192x48, K=192)
//           X streamed in 6 chunks of 32 cols via double-buffered cp.async
//   stage2: Y[n][r3*48+r2] = sum_k C_inv[r3][k] * T[k][r2]  (48x48, K=192)
// SMEM aliasing: Fs = Binv then Cinv; Xbuf(2x192x36 fp32) then Ts(48x196 tf32).
// ---------------------------------------------------------------------------
#define ENC_SMEM_U32 (48*196 + 2*192*36)
__global__ void __launch_bounds__(192, 2) k_enc(
    const float* __restrict__ X, const float* __restrict__ Binv,
    const float* __restrict__ Cinv, float* __restrict__ Y)
{
    extern __shared__ uint32_t sme[];
    uint32_t* Fs = sme;                 // 48*196 tf32: Binv, later Cinv
    float*    Xf = (float*)(sme + 48*196);  // 2 x 192 x 36 fp32; later Ts (48x196 tf32)
    uint32_t* Ts = sme + 48*196;

    const int n = blockIdx.x, tid = threadIdx.x;
    const int w = tid >> 5, lane = tid & 31;
    const int lr = lane >> 2, lc = lane & 3;

    // Load B_inv (48x192 fp32) -> tf32 SMEM [r2][j], stride 196
    for (int i = tid; i < 2304; i += 192) {
        int r = i / 48, c = (i % 48) * 4;
        float4 v = *(const float4*)(Binv + r * 192 + c);
        uint32_t* p = &Fs[r * 196 + c];
        p[0] = cvt_tf32(v.x); p[1] = cvt_tf32(v.y);
        p[2] = cvt_tf32(v.z); p[3] = cvt_tf32(v.w);
    }

    const uint32_t xs_base = (uint32_t)__cvta_generic_to_shared(Xf);
    const float* Xn = X + (size_t)n * 36864;

    // chunk loader: 192 rows x 32 cols (128B/row = 8 x 16B)
    auto load_chunk = [&](int ck, int buf) {
        const float* src = Xn + ck * 32;
        #pragma unroll
        for (int i = tid; i < 1536; i += 192) {
            int row = i >> 3, seg = i & 7;
            cp_async16(xs_base + (buf * 6912 + row * 36 + seg * 4) * 4,
                       src + row * 192 + seg * 4);
        }
        asm volatile("cp.async.commit_group;");
    };

    load_chunk(0, 0);

    float acc[2][6][4];
    #pragma unroll
    for (int i = 0; i < 2; i++)
        #pragma unroll
        for (int j = 0; j < 6; j++)
            #pragma unroll
            for (int d = 0; d < 4; d++) acc[i][j][d] = 0.f;

    for (int ck = 0; ck < 6; ck++) {
        asm volatile("cp.async.wait_group 0;" ::: "memory");
        __syncthreads();                       // chunk ck visible; prior MMA complete
        if (ck < 5) load_chunk(ck + 1, (ck + 1) & 1);
        const float* Xb = Xf + ((ck & 1) ? 6912 : 0);

        #pragma unroll
        for (int kk = 0; kk < 32; kk += 8) {
            uint32_t af[2][4], bf[6][2];
            #pragma unroll
            for (int mt = 0; mt < 2; mt++) {
                const float* pa = Xb + (w * 32 + mt * 16 + lr) * 36 + kk + lc;
                af[mt][0] = cvt_tf32(pa[0]);
                af[mt][1] = cvt_tf32(pa[288]);     // +8 rows
                af[mt][2] = cvt_tf32(pa[4]);
                af[mt][3] = cvt_tf32(pa[292]);
            }
            #pragma unroll
            for (int nt = 0; nt < 6; nt++) {
                const uint32_t* pb = &Fs[(nt * 8 + lr) * 196 + ck * 32 + kk + lc];
                bf[nt][0] = pb[0]; bf[nt][1] = pb[4];
            }
            #pragma unroll
            for (int mt = 0; mt < 2; mt++)
                #pragma unroll
                for (int nt = 0; nt < 6; nt++)
                    mma_tf32(acc[mt][nt], af[mt], bf[nt]);
        }
    }
    __syncthreads();   // stage1 done everywhere: Xbuf + Fs free for reuse

    // Store T transposed -> Ts[r2][k] (tf32, stride 196); overwrite X buffers
    #pragma unroll
    for (int mt = 0; mt < 2; mt++) {
        int k0 = w * 32 + mt * 16 + lr;
        #pragma unroll
        for (int nt = 0; nt < 6; nt++) {
            int r2 = nt * 8 + 2 * lc;
            Ts[r2 * 196 + k0]           = cvt_tf32(acc[mt][nt][0]);
            Ts[(r2 + 1) * 196 + k0]     = cvt_tf32(acc[mt][nt][1]);
            Ts[r2 * 196 + k0 + 8]       = cvt_tf32(acc[mt][nt][2]);
            Ts[(r2 + 1) * 196 + k0 + 8] = cvt_tf32(acc[mt][nt][3]);
        }
    }
    // Load C_inv over the Binv region
    for (int i = tid; i < 2304; i += 192) {
        int r = i / 48, c = (i % 48) * 4;
        float4 v = *(const float4*)(Cinv + r * 192 + c);
        uint32_t* p = &Fs[r * 196 + c];
        p[0] = cvt_tf32(v.x); p[1] = cvt_tf32(v.y);
        p[2] = cvt_tf32(v.z); p[3] = cvt_tf32(v.w);
    }
    __syncthreads();

    // stage2: Y = Cinv(48x192) @ T(192x48); 6 warps: mt2 = w%3 rows, nh = w/3 col-half
    const int mt2 = w % 3, nh = w / 3;
    float a2[3][4];
    #pragma unroll
    for (int i = 0; i < 3; i++)
        #pragma unroll
        for (int d = 0; d < 4; d++) a2[i][d] = 0.f;

    #pragma unroll 8
    for (int kk = 0; kk < 192; kk += 8) {
        uint32_t af[4];
        const uint32_t* pa = &Fs[(mt2 * 16 + lr) * 196 + kk + lc];
        af[0] = pa[0]; af[1] = pa[1568]; af[2] = pa[4]; af[3] = pa[1572];
        #pragma unroll
        for (int nt = 0; nt < 3; nt++) {
            const uint32_t* pb = &Ts[(nh * 24 + nt * 8 + lr) * 196 + kk + lc];
            uint32_t bf[2] = { pb[0], pb[4] };
            mma_tf32(a2[nt], af, bf);
        }
    }
    float* Yn = Y + (size_t)n * 2304;
    #pragma unroll
    for (int nt = 0; nt < 3; nt++) {
        int r3 = mt2 * 16 + lr;
        int r2 = nh * 24 + nt * 8 + 2 * lc;
        *(float2*)(Yn + r3 * 48 + r2)       = make_float2(a2[nt][0], a2[nt][1]);
        *(float2*)(Yn + (r3 + 8) * 48 + r2) = make_float2(a2[nt][2], a2[nt][3]);
    }
}

// ---------------------------------------------------------------------------
// Generic tf32 tensor-core GEMM:  C[M,N] = A[M,K] (fp32) @ B[N,K]^T (tf32)
// (unchanged from R3 — used for the two middle GEMMs)
// ---------------------------------------------------------------------------
template <int BM, int BN, int BK, int MW, int NW>
__global__ void __launch_bounds__(256) k_gemm_tc(
    const float* __restrict__ A, const uint32_t* __restrict__ B,
    float* __restrict__ C, int M, int N, int K)
{
    constexpr int WM = BM / MW, WN = BN / NW;
    constexpr int MT = WM / 16, NT = WN / 8;
    constexpr int LDSS = BK + 4;
    __shared__ uint32_t As[BM * LDSS];
    __shared__ uint32_t Bs[BN * LDSS];

    const int tid  = threadIdx.x;
    const int lane = tid & 31, warp = tid >> 5;
    const int wm = (warp / NW) * WM;
    const int wn = (warp % NW) * WN;
    const int m0 = blockIdx.y * BM;
    const int n0 = blockIdx.x * BN;
    const int lr = lane >> 2, lc = lane & 3;

    float acc[MT][NT][4];
    #pragma unroll
    for (int i = 0; i < MT; i++)
        #pragma unroll
        for (int j = 0; j < NT; j++)
            #pragma unroll
            for (int d = 0; d < 4; d++) acc[i][j][d] = 0.f;

    for (int k0 = 0; k0 < K; k0 += BK) {
        for (int i = tid; i < BM * BK / 4; i += 256) {
            int r = i / (BK / 4), c = (i % (BK / 4)) * 4;
            const float4 v = *(const float4*)(A + (size_t)(m0 + r) * K + k0 + c);
            uint32_t* p = &As[r * LDSS + c];
            p[0] = cvt_tf32(v.x); p[1] = cvt_tf32(v.y);
            p[2] = cvt_tf32(v.z); p[3] = cvt_tf32(v.w);
        }
        for (int i = tid; i < BN * BK / 4; i += 256) {
            int r = i / (BK / 4), c = (i % (BK / 4)) * 4;
            const uint4 v = *(const uint4*)(B + (size_t)(n0 + r) * K + k0 + c);
            uint32_t* p = &Bs[r * LDSS + c];
            p[0] = v.x; p[1] = v.y; p[2] = v.z; p[3] = v.w;
        }
        __syncthreads();

        #pragma unroll
        for (int kk = 0; kk < BK; kk += 8) {
            uint32_t af[MT][4], bf[NT][2];
            #pragma unroll
            for (int mt = 0; mt < MT; mt++) {
                const uint32_t* p = &As[(wm + mt * 16 + lr) * LDSS + kk + lc];
                af[mt][0] = p[0];
                af[mt][1] = p[8 * LDSS];
                af[mt][2] = p[4];
                af[mt][3] = p[8 * LDSS + 4];
            }
            #pragma unroll
            for (int nt = 0; nt < NT; nt++) {
                const uint32_t* p = &Bs[(wn + nt * 8 + lr) * LDSS + kk + lc];
                bf[nt][0] = p[0];
                bf[nt][1] = p[4];
            }
            #pragma unroll
            for (int mt = 0; mt < MT; mt++)
                #pragma unroll
                for (int nt = 0; nt < NT; nt++)
                    mma_tf32(acc[mt][nt], af[mt], bf[nt]);
        }
        __syncthreads();
    }

    #pragma unroll
    for (int mt = 0; mt < MT; mt++) {
        int r0 = m0 + wm + mt * 16 + lr;
        #pragma unroll
        for (int nt = 0; nt < NT; nt++) {
            int c0 = n0 + wn + nt * 8 + 2 * lc;
            *(float2*)(C + (size_t)r0 * N + c0)       = make_float2(acc[mt][nt][0], acc[mt][nt][1]);
            *(float2*)(C + (size_t)(r0 + 8) * N + c0) = make_float2(acc[mt][nt][2], acc[mt][nt][3]);
        }
    }
}

// ---------------------------------------------------------------------------
// Row softmax for A (2048 x 256), fp32.
// ---------------------------------------------------------------------------
__global__ void __launch_bounds__(256) k_softmaxA(
    const float* __restrict__ A, float* __restrict__ out)
{
    __shared__ float red[8];
    int n = blockIdx.x, t = threadIdx.x;
    float v = A[(size_t)n * 256 + t];
    float m = v;
    #pragma unroll
    for (int o = 16; o > 0; o >>= 1) m = fmaxf(m, __shfl_xor_sync(0xffffffffu, m, o));
    if ((t & 31) == 0) red[t >> 5] = m;
    __syncthreads();
    float bm = red[0];
    #pragma unroll
    for (int i = 1; i < 8; i++) bm = fmaxf(bm, red[i]);
    float e = expf(v - bm);
    float s = e;
    #pragma unroll
    for (int o = 16; o > 0; o >>= 1) s += __shfl_xor_sync(0xffffffffu, s, o);
    __syncthreads();
    if ((t & 31) == 0) red[t >> 5] = s;
    __syncthreads();
    float bs = 0.f;
    #pragma unroll
    for (int i = 0; i < 8; i++) bs += red[i];
    out[(size_t)n * 256 + t] = e / bs;
}

// ---------------------------------------------------------------------------
// Fused decode: one CTA per sample n (192 threads = 6 warps).
//   stage1: U[k][r2] = sum_r3 smC[k][r3] * S[n][r3*48+r2]   (192x48, K=48)
//   stage2: out[n][k*192+j] = sum_r2 U[k][r2] * smB[j][r2]  (192x192, K=48)
// SMEM aliasing: Cs = smC (192x52) then Ua (192x52); St (48x52); Bsm (192x52).
// ---------------------------------------------------------------------------
#define DEC_SMEM_U32 (192*52 + 48*52 + 192*52)
__global__ void __launch_bounds__(192, 2) k_dec(
    const float* __restrict__ S, const uint32_t* __restrict__ smB,
    const uint32_t* __restrict__ smC, float* __restrict__ out)
{
    extern __shared__ uint32_t smd[];
    uint32_t* Cs  = smd;                 // smC [k][r3] then Ua [k][r2]
    uint32_t* St  = smd + 192 * 52;      // S^T  [r2][r3]
    uint32_t* Bsm = smd + 192 * 52 + 48 * 52;   // smB [j][r2]

    const int n = blockIdx.x, tid = threadIdx.x;
    const int w = tid >> 5, lane = tid & 31;
    const int lr = lane >> 2, lc = lane & 3;

    for (int i = tid; i < 2304; i += 192) {
        int r = i / 12, c = (i % 12) * 4;
        uint4 v = *(const uint4*)(smC + r * 48 + c);
        uint32_t* p = &Cs[r * 52 + c];
        p[0] = v.x; p[1] = v.y; p[2] = v.z; p[3] = v.w;
    }
    for (int i = tid; i < 2304; i += 192) {
        int r = i / 12, c = (i % 12) * 4;
        uint4 v = *(const uint4*)(smB + r * 48 + c);
        uint32_t* p = &Bsm[r * 52 + c];
        p[0] = v.x; p[1] = v.y; p[2] = v.z; p[3] = v.w;
    }
    const float* Sn = S + (size_t)n * 2304;
    for (int i = tid; i < 576; i += 192) {
        int r3 = i / 12, r2 = (i % 12) * 4;
        float4 v = *(const float4*)(Sn + r3 * 48 + r2);
        St[(r2 + 0) * 52 + r3] = cvt_tf32(v.x);
        St[(r2 + 1) * 52 + r3] = cvt_tf32(v.y);
        St[(r2 + 2) * 52 + r3] = cvt_tf32(v.z);
        St[(r2 + 3) * 52 + r3] = cvt_tf32(v.w);
    }
    __syncthreads();

    // stage1: warp w -> rows k in [w*32, w*32+32)
    float a1[2][6][4];
    #pragma unroll
    for (int i = 0; i < 2; i++)
        #pragma unroll
        for (int j = 0; j < 6; j++)
            #pragma unroll
            for (int d = 0; d < 4; d++) a1[i][j][d] = 0.f;

    #pragma unroll
    for (int kk = 0; kk < 48; kk += 8) {
        uint32_t af[2][4], bf[6][2];
        #pragma unroll
        for (int mt = 0; mt < 2; mt++) {
            const uint32_t* pa = &Cs[(w * 32 + mt * 16 + lr) * 52 + kk + lc];
            af[mt][0] = pa[0]; af[mt][1] = pa[416];
            af[mt][2] = pa[4]; af[mt][3] = pa[420];
        }
        #pragma unroll
        for (int nt = 0; nt < 6; nt++) {
            const uint32_t* pb = &St[(nt * 8 + lr) * 52 + kk + lc];
            bf[nt][0] = pb[0]; bf[nt][1] = pb[4];
        }
        #pragma unroll
        for (int mt = 0; mt < 2; mt++)
            #pragma unroll
            for (int nt = 0; nt < 6; nt++)
                mma_tf32(a1[mt][nt], af[mt], bf[nt]);
    }
    __syncthreads();   // smC reads done -> reuse Cs as Ua

    #pragma unroll
    for (int mt = 0; mt < 2; mt++) {
        int k0 = w * 32 + mt * 16 + lr;
        #pragma unroll
        for (int nt = 0; nt < 6; nt++) {
            int r2 = nt * 8 + 2 * lc;
            Cs[k0 * 52 + r2]           = cvt_tf32(a1[mt][nt][0]);
            Cs[k0 * 52 + r2 + 1]       = cvt_tf32(a1[mt][nt][1]);
            Cs[(k0 + 8) * 52 + r2]     = cvt_tf32(a1[mt][nt][2]);
            Cs[(k0 + 8) * 52 + r2 + 1] = cvt_tf32(a1[mt][nt][3]);
        }
    }
    __syncthreads();

    // stage2: out tile 192x192 in two N-passes of 96; warp grid 3(m) x 2(n)
    float* on = out + (size_t)n * 36864;
    const int wm = (w % 3) * 64;
    #pragma unroll
    for (int np = 0; np < 2; np++) {
        const int wn = (w / 3) * 48 + np * 96;
        float a2[4][6][4];
        #pragma unroll
        for (int i = 0; i < 4; i++)
            #pragma unroll
            for (int j = 0; j < 6; j++)
                #pragma unroll
                for (int d = 0; d < 4; d++) a2[i][j][d] = 0.f;

        #pragma unroll
        for (int kk = 0; kk < 48; kk += 8) {
            uint32_t af[4][4], bf[6][2];
            #pragma unroll
            for (int mt = 0; mt < 4; mt++) {
                const uint32_t* pa = &Cs[(wm + mt * 16 + lr) * 52 + kk + lc];
                af[mt][0] = pa[0]; af[mt][1] = pa[416];
                af[mt][2] = pa[4]; af[mt][3] = pa[420];
            }
            #pragma unroll
            for (int nt = 0; nt < 6; nt++) {
                const uint32_t* pb = &Bsm[(wn + nt * 8 + lr) * 52 + kk + lc];
                bf[nt][0] = pb[0]; bf[nt][1] = pb[4];
            }
            #pragma unroll
            for (int mt = 0; mt < 4; mt++)
                #pragma unroll
                for (int nt = 0; nt < 6; nt++)
                    mma_tf32(a2[mt][nt], af[mt], bf[nt]);
        }
        #pragma unroll
        for (int mt = 0; mt < 4; mt++) {
            int row = wm + mt * 16 + lr;
            #pragma unroll
            for (int nt = 0; nt < 6; nt++) {
                int col = wn + nt * 8 + 2 * lc;
                *(float2*)(on + (size_t)row * 192 + col) =
                    make_float2(a2[mt][nt][0], a2[mt][nt][1]);
                *(float2*)(on + (size_t)(row + 8) * 192 + col) =
                    make_float2(a2[mt][nt][2], a2[mt][nt][3]);
            }
        }
    }
}

// ---------------------------------------------------------------------------
// Launch pipeline (default stream -> sequential; graph-capturable)
// ---------------------------------------------------------------------------
extern "C" void kernel_launch(void* const* d_in, const int* in_sizes, int n_in,
                              void* d_out, int out_size)
{
    const float* X     = (const float*)d_in[0];
    const float* B     = (const float*)d_in[1];
    const float* C     = (const float*)d_in[2];
    const float* G     = (const float*)d_in[3];
    const float* B_inv = (const float*)d_in[4];
    const float* C_inv = (const float*)d_in[5];
    const float* G_inv = (const float*)d_in[6];
    float* out = (float*)d_out;

    float *pBuf2, *pA, *pSmA;
    uint32_t *pSmBT, *pSmCT, *pGt, *pGrt;
    cudaGetSymbolAddress((void**)&pBuf2, g_buf2);
    cudaGetSymbolAddress((void**)&pA,    g_Amat);
    cudaGetSymbolAddress((void**)&pSmA,  g_smA);
    cudaGetSymbolAddress((void**)&pSmBT, g_smBT);
    cudaGetSymbolAddress((void**)&pSmCT, g_smCT);
    cudaGetSymbolAddress((void**)&pGt,   g_Gt);
    cudaGetSymbolAddress((void**)&pGrt,  g_Grt);

    cudaFuncSetAttribute(k_enc, cudaFuncAttributeMaxDynamicSharedMemorySize, ENC_SMEM_U32 * 4);
    cudaFuncSetAttribute(k_dec, cudaFuncAttributeMaxDynamicSharedMemorySize, DEC_SMEM_U32 * 4);

    // prep (independent of X)
    k_prep<<<1154, 256>>>(G_inv, G, B, C, pGt, pGrt, pSmBT, pSmCT);

    // encode: Y[n] = C_inv @ (X[n] @ B_inv^T)
    k_enc<<<2048, 192, ENC_SMEM_U32 * 4>>>(X, B_inv, C_inv, pBuf2);

    // A = Y(2048x2304) @ G_inv(2304x256); softmax rows
    k_gemm_tc<64, 64, 32, 2, 4><<<dim3(4, 32), 256>>>(pBuf2, pGt, pA, 2048, 256, 2304);
    k_softmaxA<<<2048, 256>>>(pA, pSmA);

    // S = smA(2048x256) @ relu(G)(256x2304)
    k_gemm_tc<128, 128, 32, 4, 2><<<dim3(18, 16), 256>>>(pSmA, pGrt, pBuf2, 2048, 2304, 256);

    // decode: out[n] = (smC @ S[n]) @ smB^T
    k_dec<<<2048, 192, DEC_SMEM_U32 * 4>>>(pBuf2, pSmBT, pSmCT, out);
}

// round 5
// speedup vs baseline: 4.1798x; 1.4387x over previous
#include <cuda_runtime.h>
#include <cstdint>
#include <cstddef>

// Problem dims (fixed)
#define NSAMP 2048
#define JDIM  192
#define KDIM  192
#define R1D   256
#define R2D   48
#define R3D   48

// ---------------------------------------------------------------------------
// Scratch (__device__ globals; no allocation)
// ---------------------------------------------------------------------------
__device__ __align__(16) float    g_buf2[(size_t)NSAMP * R2D * R3D];    // Y then S (18MB)
__device__ __align__(16) float    g_Amat[(size_t)NSAMP * R1D];
__device__ __align__(16) float    g_smA [(size_t)NSAMP * R1D];
__device__ __align__(16) uint32_t g_smBT [JDIM * R2D];     // tf32 softmax(B) (192x48)
__device__ __align__(16) uint32_t g_smCT [KDIM * R3D];     // tf32 softmax(C) (192x48)
__device__ __align__(16) uint32_t g_Gt   [R1D * 2304];     // tf32 G_inv^T (256x2304)
__device__ __align__(16) uint32_t g_Grt  [2304 * R1D];     // tf32 relu(G)^T (2304x256)

// ---------------------------------------------------------------------------
// tf32 helpers
// ---------------------------------------------------------------------------
__device__ __forceinline__ uint32_t cvt_tf32(float x) {
    uint32_t r;
    asm("cvt.rna.tf32.f32 %0, %1;" : "=r"(r) : "f"(x));
    return r;
}

__device__ __forceinline__ void mma_tf32(float* d, const uint32_t* a, const uint32_t* b) {
    asm volatile(
        "mma.sync.aligned.m16n8k8.row.col.f32.tf32.tf32.f32 "
        "{%0,%1,%2,%3},{%4,%5,%6,%7},{%8,%9},{%0,%1,%2,%3};"
        : "+f"(d[0]), "+f"(d[1]), "+f"(d[2]), "+f"(d[3])
        : "r"(a[0]), "r"(a[1]), "r"(a[2]), "r"(a[3]), "r"(b[0]), "r"(b[1]));
}

__device__ __forceinline__ void cp_async16(uint32_t smem_dst, const void* gsrc) {
    asm volatile("cp.async.cg.shared.global [%0], [%1], 16;" :: "r"(smem_dst), "l"(gsrc));
}

// ---------------------------------------------------------------------------
// Fused prep: G_inv^T, relu(G)^T (tiled coalesced transposes) + both softmaxes.
// ---------------------------------------------------------------------------
__global__ void __launch_bounds__(256) k_prep(
    const float* __restrict__ Gi, const float* __restrict__ G,
    const float* __restrict__ B,  const float* __restrict__ C,
    uint32_t* __restrict__ Gt, uint32_t* __restrict__ Grt,
    uint32_t* __restrict__ smBT, uint32_t* __restrict__ smCT)
{
    __shared__ float tile[32][33];
    const int b = blockIdx.x, tid = threadIdx.x;
    const int tx = tid & 31, ty = tid >> 5;

    if (b < 576) {
        int br = b >> 3, bc = b & 7;
        #pragma unroll
        for (int i = 0; i < 4; i++)
            tile[ty + 8*i][tx] = Gi[(size_t)(br*32 + ty + 8*i) * 256 + bc*32 + tx];
        __syncthreads();
        #pragma unroll
        for (int i = 0; i < 4; i++)
            Gt[(size_t)(bc*32 + ty + 8*i) * 2304 + br*32 + tx] = cvt_tf32(tile[tx][ty + 8*i]);
    } else if (b < 1152) {
        int b2 = b - 576;
        int br = b2 & 7, bc = b2 >> 3;
        #pragma unroll
        for (int i = 0; i < 4; i++)
            tile[ty + 8*i][tx] = G[(size_t)(br*32 + ty + 8*i) * 2304 + bc*32 + tx];
        __syncthreads();
        #pragma unroll
        for (int i = 0; i < 4; i++)
            Grt[(size_t)(bc*32 + ty + 8*i) * 256 + br*32 + tx] =
                cvt_tf32(fmaxf(tile[tx][ty + 8*i], 0.f));
    } else {
        const float* in = (b == 1152) ? B : C;
        uint32_t* out = (b == 1152) ? smBT : smCT;
        int r = tid;
        if (r < 192) {
            const float* p = in + r * 48;
            float m = -1e30f;
            #pragma unroll
            for (int j = 0; j < 48; j++) m = fmaxf(m, p[j]);
            float e[48], s = 0.f;
            #pragma unroll
            for (int j = 0; j < 48; j++) { e[j] = expf(p[j] - m); s += e[j]; }
            float inv = 1.f / s;
            #pragma unroll
            for (int j = 0; j < 48; j++) out[r * 48 + j] = cvt_tf32(e[j] * inv);
        }
    }
}

// ---------------------------------------------------------------------------
// Fused encode: one CTA per sample n (192 threads = 6 warps).  (unchanged)
// ---------------------------------------------------------------------------
#define ENC_SMEM_U32 (48*196 + 2*192*36)
__global__ void __launch_bounds__(192, 2) k_enc(
    const float* __restrict__ X, const float* __restrict__ Binv,
    const float* __restrict__ Cinv, float* __restrict__ Y)
{
    extern __shared__ uint32_t sme[];
    uint32_t* Fs = sme;                 // 48*196 tf32: Binv, later Cinv
    float*    Xf = (float*)(sme + 48*196);  // 2 x 192 x 36 fp32; later Ts
    uint32_t* Ts = sme + 48*196;

    const int n = blockIdx.x, tid = threadIdx.x;
    const int w = tid >> 5, lane = tid & 31;
    const int lr = lane >> 2, lc = lane & 3;

    for (int i = tid; i < 2304; i += 192) {
        int r = i / 48, c = (i % 48) * 4;
        float4 v = *(const float4*)(Binv + r * 192 + c);
        uint32_t* p = &Fs[r * 196 + c];
        p[0] = cvt_tf32(v.x); p[1] = cvt_tf32(v.y);
        p[2] = cvt_tf32(v.z); p[3] = cvt_tf32(v.w);
    }

    const uint32_t xs_base = (uint32_t)__cvta_generic_to_shared(Xf);
    const float* Xn = X + (size_t)n * 36864;

    auto load_chunk = [&](int ck, int buf) {
        const float* src = Xn + ck * 32;
        #pragma unroll
        for (int i = tid; i < 1536; i += 192) {
            int row = i >> 3, seg = i & 7;
            cp_async16(xs_base + (buf * 6912 + row * 36 + seg * 4) * 4,
                       src + row * 192 + seg * 4);
        }
        asm volatile("cp.async.commit_group;");
    };

    load_chunk(0, 0);

    float acc[2][6][4];
    #pragma unroll
    for (int i = 0; i < 2; i++)
        #pragma unroll
        for (int j = 0; j < 6; j++)
            #pragma unroll
            for (int d = 0; d < 4; d++) acc[i][j][d] = 0.f;

    for (int ck = 0; ck < 6; ck++) {
        asm volatile("cp.async.wait_group 0;" ::: "memory");
        __syncthreads();
        if (ck < 5) load_chunk(ck + 1, (ck + 1) & 1);
        const float* Xb = Xf + ((ck & 1) ? 6912 : 0);

        #pragma unroll
        for (int kk = 0; kk < 32; kk += 8) {
            uint32_t af[2][4], bf[6][2];
            #pragma unroll
            for (int mt = 0; mt < 2; mt++) {
                const float* pa = Xb + (w * 32 + mt * 16 + lr) * 36 + kk + lc;
                af[mt][0] = cvt_tf32(pa[0]);
                af[mt][1] = cvt_tf32(pa[288]);
                af[mt][2] = cvt_tf32(pa[4]);
                af[mt][3] = cvt_tf32(pa[292]);
            }
            #pragma unroll
            for (int nt = 0; nt < 6; nt++) {
                const uint32_t* pb = &Fs[(nt * 8 + lr) * 196 + ck * 32 + kk + lc];
                bf[nt][0] = pb[0]; bf[nt][1] = pb[4];
            }
            #pragma unroll
            for (int mt = 0; mt < 2; mt++)
                #pragma unroll
                for (int nt = 0; nt < 6; nt++)
                    mma_tf32(acc[mt][nt], af[mt], bf[nt]);
        }
    }
    __syncthreads();

    #pragma unroll
    for (int mt = 0; mt < 2; mt++) {
        int k0 = w * 32 + mt * 16 + lr;
        #pragma unroll
        for (int nt = 0; nt < 6; nt++) {
            int r2 = nt * 8 + 2 * lc;
            Ts[r2 * 196 + k0]           = cvt_tf32(acc[mt][nt][0]);
            Ts[(r2 + 1) * 196 + k0]     = cvt_tf32(acc[mt][nt][1]);
            Ts[r2 * 196 + k0 + 8]       = cvt_tf32(acc[mt][nt][2]);
            Ts[(r2 + 1) * 196 + k0 + 8] = cvt_tf32(acc[mt][nt][3]);
        }
    }
    for (int i = tid; i < 2304; i += 192) {
        int r = i / 48, c = (i % 48) * 4;
        float4 v = *(const float4*)(Cinv + r * 192 + c);
        uint32_t* p = &Fs[r * 196 + c];
        p[0] = cvt_tf32(v.x); p[1] = cvt_tf32(v.y);
        p[2] = cvt_tf32(v.z); p[3] = cvt_tf32(v.w);
    }
    __syncthreads();

    const int mt2 = w % 3, nh = w / 3;
    float a2[3][4];
    #pragma unroll
    for (int i = 0; i < 3; i++)
        #pragma unroll
        for (int d = 0; d < 4; d++) a2[i][d] = 0.f;

    #pragma unroll 8
    for (int kk = 0; kk < 192; kk += 8) {
        uint32_t af[4];
        const uint32_t* pa = &Fs[(mt2 * 16 + lr) * 196 + kk + lc];
        af[0] = pa[0]; af[1] = pa[1568]; af[2] = pa[4]; af[3] = pa[1572];
        #pragma unroll
        for (int nt = 0; nt < 3; nt++) {
            const uint32_t* pb = &Ts[(nh * 24 + nt * 8 + lr) * 196 + kk + lc];
            uint32_t bf[2] = { pb[0], pb[4] };
            mma_tf32(a2[nt], af, bf);
        }
    }
    float* Yn = Y + (size_t)n * 2304;
    #pragma unroll
    for (int nt = 0; nt < 3; nt++) {
        int r3 = mt2 * 16 + lr;
        int r2 = nh * 24 + nt * 8 + 2 * lc;
        *(float2*)(Yn + r3 * 48 + r2)       = make_float2(a2[nt][0], a2[nt][1]);
        *(float2*)(Yn + (r3 + 8) * 48 + r2) = make_float2(a2[nt][2], a2[nt][3]);
    }
}

// ---------------------------------------------------------------------------
// Pipelined tf32 TC GEMM:  C[M,N] = A[M,K] (fp32) @ B[N,K]^T (tf32)
// 2-stage cp.async double buffering. A staged raw fp32, cvt at fragment load.
// Dynamic SMEM: 2*BM*LDSS floats (A) + 2*BN*LDSS u32 (B), LDSS=BK+4.
// ---------------------------------------------------------------------------
template <int BM, int BN, int BK, int MW, int NW>
__global__ void __launch_bounds__(256) k_gemm_tc_p(
    const float* __restrict__ A, const uint32_t* __restrict__ B,
    float* __restrict__ C, int M, int N, int K)
{
    constexpr int WM = BM / MW, WN = BN / NW;
    constexpr int MT = WM / 16, NT = WN / 8;
    constexpr int LDSS = BK + 4;
    extern __shared__ uint32_t smg[];
    float*    As = (float*)smg;              // 2 x BM x LDSS
    uint32_t* Bs = smg + 2 * BM * LDSS;      // 2 x BN x LDSS

    const int tid  = threadIdx.x;
    const int lane = tid & 31, warp = tid >> 5;
    const int wm = (warp / NW) * WM;
    const int wn = (warp % NW) * WN;
    const int m0 = blockIdx.y * BM;
    const int n0 = blockIdx.x * BN;
    const int lr = lane >> 2, lc = lane & 3;

    const uint32_t as_base = (uint32_t)__cvta_generic_to_shared(As);
    const uint32_t bs_base = (uint32_t)__cvta_generic_to_shared(Bs);

    auto load_stage = [&](int it, int buf) {
        const int k0 = it * BK;
        #pragma unroll
        for (int i = tid; i < BM * BK / 4; i += 256) {
            int r = i / (BK / 4), s = (i % (BK / 4)) * 4;
            cp_async16(as_base + (buf * BM * LDSS + r * LDSS + s) * 4,
                       A + (size_t)(m0 + r) * K + k0 + s);
        }
        #pragma unroll
        for (int i = tid; i < BN * BK / 4; i += 256) {
            int r = i / (BK / 4), s = (i % (BK / 4)) * 4;
            cp_async16(bs_base + (buf * BN * LDSS + r * LDSS + s) * 4,
                       B + (size_t)(n0 + r) * K + k0 + s);
        }
        asm volatile("cp.async.commit_group;");
    };

    float acc[MT][NT][4];
    #pragma unroll
    for (int i = 0; i < MT; i++)
        #pragma unroll
        for (int j = 0; j < NT; j++)
            #pragma unroll
            for (int d = 0; d < 4; d++) acc[i][j][d] = 0.f;

    load_stage(0, 0);
    const int iters = K / BK;

    for (int it = 0; it < iters; it++) {
        asm volatile("cp.async.wait_group 0;" ::: "memory");
        __syncthreads();
        if (it + 1 < iters) load_stage(it + 1, (it + 1) & 1);
        const float*    Ab = As + (it & 1) * BM * LDSS;
        const uint32_t* Bb = Bs + (it & 1) * BN * LDSS;

        #pragma unroll
        for (int kk = 0; kk < BK; kk += 8) {
            uint32_t af[MT][4], bf[NT][2];
            #pragma unroll
            for (int mt = 0; mt < MT; mt++) {
                const float* pa = Ab + (wm + mt * 16 + lr) * LDSS + kk + lc;
                af[mt][0] = cvt_tf32(pa[0]);
                af[mt][1] = cvt_tf32(pa[8 * LDSS]);
                af[mt][2] = cvt_tf32(pa[4]);
                af[mt][3] = cvt_tf32(pa[8 * LDSS + 4]);
            }
            #pragma unroll
            for (int nt = 0; nt < NT; nt++) {
                const uint32_t* pb = Bb + (wn + nt * 8 + lr) * LDSS + kk + lc;
                bf[nt][0] = pb[0];
                bf[nt][1] = pb[4];
            }
            #pragma unroll
            for (int mt = 0; mt < MT; mt++)
                #pragma unroll
                for (int nt = 0; nt < NT; nt++)
                    mma_tf32(acc[mt][nt], af[mt], bf[nt]);
        }
    }

    #pragma unroll
    for (int mt = 0; mt < MT; mt++) {
        int r0 = m0 + wm + mt * 16 + lr;
        #pragma unroll
        for (int nt = 0; nt < NT; nt++) {
            int c0 = n0 + wn + nt * 8 + 2 * lc;
            *(float2*)(C + (size_t)r0 * N + c0)       = make_float2(acc[mt][nt][0], acc[mt][nt][1]);
            *(float2*)(C + (size_t)(r0 + 8) * N + c0) = make_float2(acc[mt][nt][2], acc[mt][nt][3]);
        }
    }
}

#define GEMMA_SMEM ((2*64*68 + 2*32*68) * 4)
#define GEMMS_SMEM ((2*128*36 + 2*128*36) * 4)

// ---------------------------------------------------------------------------
// Row softmax for A (2048 x 256), fp32.
// ---------------------------------------------------------------------------
__global__ void __launch_bounds__(256) k_softmaxA(
    const float* __restrict__ A, float* __restrict__ out)
{
    __shared__ float red[8];
    int n = blockIdx.x, t = threadIdx.x;
    float v = A[(size_t)n * 256 + t];
    float m = v;
    #pragma unroll
    for (int o = 16; o > 0; o >>= 1) m = fmaxf(m, __shfl_xor_sync(0xffffffffu, m, o));
    if ((t & 31) == 0) red[t >> 5] = m;
    __syncthreads();
    float bm = red[0];
    #pragma unroll
    for (int i = 1; i < 8; i++) bm = fmaxf(bm, red[i]);
    float e = expf(v - bm);
    float s = e;
    #pragma unroll
    for (int o = 16; o > 0; o >>= 1) s += __shfl_xor_sync(0xffffffffu, s, o);
    __syncthreads();
    if ((t & 31) == 0) red[t >> 5] = s;
    __syncthreads();
    float bs = 0.f;
    #pragma unroll
    for (int i = 0; i < 8; i++) bs += red[i];
    out[(size_t)n * 256 + t] = e / bs;
}

// ---------------------------------------------------------------------------
// Fused decode: one CTA per sample n (192 threads = 6 warps).
// stage2 split into 4 N-passes (48 acc regs live) to avoid spills.
// ---------------------------------------------------------------------------
#define DEC_SMEM_U32 (192*52 + 48*52 + 192*52)
__global__ void __launch_bounds__(192, 2) k_dec(
    const float* __restrict__ S, const uint32_t* __restrict__ smB,
    const uint32_t* __restrict__ smC, float* __restrict__ out)
{
    extern __shared__ uint32_t smd[];
    uint32_t* Cs  = smd;                 // smC [k][r3] then Ua [k][r2]
    uint32_t* St  = smd + 192 * 52;      // S^T  [r2][r3]
    uint32_t* Bsm = smd + 192 * 52 + 48 * 52;   // smB [j][r2]

    const int n = blockIdx.x, tid = threadIdx.x;
    const int w = tid >> 5, lane = tid & 31;
    const int lr = lane >> 2, lc = lane & 3;

    for (int i = tid; i < 2304; i += 192) {
        int r = i / 12, c = (i % 12) * 4;
        uint4 v = *(const uint4*)(smC + r * 48 + c);
        uint32_t* p = &Cs[r * 52 + c];
        p[0] = v.x; p[1] = v.y; p[2] = v.z; p[3] = v.w;
    }
    for (int i = tid; i < 2304; i += 192) {
        int r = i / 12, c = (i % 12) * 4;
        uint4 v = *(const uint4*)(smB + r * 48 + c);
        uint32_t* p = &Bsm[r * 52 + c];
        p[0] = v.x; p[1] = v.y; p[2] = v.z; p[3] = v.w;
    }
    const float* Sn = S + (size_t)n * 2304;
    for (int i = tid; i < 576; i += 192) {
        int r3 = i / 12, r2 = (i % 12) * 4;
        float4 v = *(const float4*)(Sn + r3 * 48 + r2);
        St[(r2 + 0) * 52 + r3] = cvt_tf32(v.x);
        St[(r2 + 1) * 52 + r3] = cvt_tf32(v.y);
        St[(r2 + 2) * 52 + r3] = cvt_tf32(v.z);
        St[(r2 + 3) * 52 + r3] = cvt_tf32(v.w);
    }
    __syncthreads();

    // stage1: U[k][r2], warp w -> rows k in [w*32, w*32+32)
    float a1[2][6][4];
    #pragma unroll
    for (int i = 0; i < 2; i++)
        #pragma unroll
        for (int j = 0; j < 6; j++)
            #pragma unroll
            for (int d = 0; d < 4; d++) a1[i][j][d] = 0.f;

    #pragma unroll
    for (int kk = 0; kk < 48; kk += 8) {
        uint32_t af[2][4], bf[6][2];
        #pragma unroll
        for (int mt = 0; mt < 2; mt++) {
            const uint32_t* pa = &Cs[(w * 32 + mt * 16 + lr) * 52 + kk + lc];
            af[mt][0] = pa[0]; af[mt][1] = pa[416];
            af[mt][2] = pa[4]; af[mt][3] = pa[420];
        }
        #pragma unroll
        for (int nt = 0; nt < 6; nt++) {
            const uint32_t* pb = &St[(nt * 8 + lr) * 52 + kk + lc];
            bf[nt][0] = pb[0]; bf[nt][1] = pb[4];
        }
        #pragma unroll
        for (int mt = 0; mt < 2; mt++)
            #pragma unroll
            for (int nt = 0; nt < 6; nt++)
                mma_tf32(a1[mt][nt], af[mt], bf[nt]);
    }
    __syncthreads();   // smC reads done -> reuse Cs as Ua

    #pragma unroll
    for (int mt = 0; mt < 2; mt++) {
        int k0 = w * 32 + mt * 16 + lr;
        #pragma unroll
        for (int nt = 0; nt < 6; nt++) {
            int r2 = nt * 8 + 2 * lc;
            Cs[k0 * 52 + r2]           = cvt_tf32(a1[mt][nt][0]);
            Cs[k0 * 52 + r2 + 1]       = cvt_tf32(a1[mt][nt][1]);
            Cs[(k0 + 8) * 52 + r2]     = cvt_tf32(a1[mt][nt][2]);
            Cs[(k0 + 8) * 52 + r2 + 1] = cvt_tf32(a1[mt][nt][3]);
        }
    }
    __syncthreads();

    // stage2: out tile 192x192, 4 N-passes of 24 cols per warp.
    float* on = out + (size_t)n * 36864;
    const int wm = (w % 3) * 64;
    const int nb = (w / 3) * 24;
    #pragma unroll
    for (int pass = 0; pass < 4; pass++) {
        const int wn = nb + pass * 48;
        float a2[4][3][4];
        #pragma unroll
        for (int i = 0; i < 4; i++)
            #pragma unroll
            for (int j = 0; j < 3; j++)
                #pragma unroll
                for (int d = 0; d < 4; d++) a2[i][j][d] = 0.f;

        #pragma unroll
        for (int kk = 0; kk < 48; kk += 8) {
            uint32_t af[4][4], bf[3][2];
            #pragma unroll
            for (int mt = 0; mt < 4; mt++) {
                const uint32_t* pa = &Cs[(wm + mt * 16 + lr) * 52 + kk + lc];
                af[mt][0] = pa[0]; af[mt][1] = pa[416];
                af[mt][2] = pa[4]; af[mt][3] = pa[420];
            }
            #pragma unroll
            for (int nt = 0; nt < 3; nt++) {
                const uint32_t* pb = &Bsm[(wn + nt * 8 + lr) * 52 + kk + lc];
                bf[nt][0] = pb[0]; bf[nt][1] = pb[4];
            }
            #pragma unroll
            for (int mt = 0; mt < 4; mt++)
                #pragma unroll
                for (int nt = 0; nt < 3; nt++)
                    mma_tf32(a2[mt][nt], af[mt], bf[nt]);
        }
        #pragma unroll
        for (int mt = 0; mt < 4; mt++) {
            int row = wm + mt * 16 + lr;
            #pragma unroll
            for (int nt = 0; nt < 3; nt++) {
                int col = wn + nt * 8 + 2 * lc;
                *(float2*)(on + (size_t)row * 192 + col) =
                    make_float2(a2[mt][nt][0], a2[mt][nt][1]);
                *(float2*)(on + (size_t)(row + 8) * 192 + col) =
                    make_float2(a2[mt][nt][2], a2[mt][nt][3]);
            }
        }
    }
}

// ---------------------------------------------------------------------------
// Launch pipeline (default stream -> sequential; graph-capturable)
// ---------------------------------------------------------------------------
extern "C" void kernel_launch(void* const* d_in, const int* in_sizes, int n_in,
                              void* d_out, int out_size)
{
    const float* X     = (const float*)d_in[0];
    const float* B     = (const float*)d_in[1];
    const float* C     = (const float*)d_in[2];
    const float* G     = (const float*)d_in[3];
    const float* B_inv = (const float*)d_in[4];
    const float* C_inv = (const float*)d_in[5];
    const float* G_inv = (const float*)d_in[6];
    float* out = (float*)d_out;

    float *pBuf2, *pA, *pSmA;
    uint32_t *pSmBT, *pSmCT, *pGt, *pGrt;
    cudaGetSymbolAddress((void**)&pBuf2, g_buf2);
    cudaGetSymbolAddress((void**)&pA,    g_Amat);
    cudaGetSymbolAddress((void**)&pSmA,  g_smA);
    cudaGetSymbolAddress((void**)&pSmBT, g_smBT);
    cudaGetSymbolAddress((void**)&pSmCT, g_smCT);
    cudaGetSymbolAddress((void**)&pGt,   g_Gt);
    cudaGetSymbolAddress((void**)&pGrt,  g_Grt);

    cudaFuncSetAttribute(k_enc, cudaFuncAttributeMaxDynamicSharedMemorySize, ENC_SMEM_U32 * 4);
    cudaFuncSetAttribute(k_dec, cudaFuncAttributeMaxDynamicSharedMemorySize, DEC_SMEM_U32 * 4);
    cudaFuncSetAttribute((const void*)k_gemm_tc_p<64, 32, 64, 4, 2>,
                         cudaFuncAttributeMaxDynamicSharedMemorySize, GEMMA_SMEM);
    cudaFuncSetAttribute((const void*)k_gemm_tc_p<128, 128, 32, 4, 2>,
                         cudaFuncAttributeMaxDynamicSharedMemorySize, GEMMS_SMEM);

    // prep (independent of X)
    k_prep<<<1154, 256>>>(G_inv, G, B, C, pGt, pGrt, pSmBT, pSmCT);

    // encode: Y[n] = C_inv @ (X[n] @ B_inv^T)
    k_enc<<<2048, 192, ENC_SMEM_U32 * 4>>>(X, B_inv, C_inv, pBuf2);

    // A = Y(2048x2304) @ G_inv(2304x256); softmax rows
    k_gemm_tc_p<64, 32, 64, 4, 2><<<dim3(8, 32), 256, GEMMA_SMEM>>>(
        pBuf2, pGt, pA, 2048, 256, 2304);
    k_softmaxA<<<2048, 256>>>(pA, pSmA);

    // S = smA(2048x256) @ relu(G)(256x2304)
    k_gemm_tc_p<128, 128, 32, 4, 2><<<dim3(18, 16), 256, GEMMS_SMEM>>>(
        pSmA, pGrt, pBuf2, 2048, 2304, 256);

    // decode: out[n] = (smC @ S[n]) @ smB^T
    k_dec<<<2048, 192, DEC_SMEM_U32 * 4>>>(pBuf2, pSmBT, pSmCT, out);
}